// round 7
// baseline (speedup 1.0000x reference)
#include <cuda_runtime.h>

#define T_WARM 48
#define OUT_STEPS 24
#define UNITS 32
#define NTHREADS 128   // 4 warps = 4 batch elements per block

typedef unsigned long long u64;

__device__ __forceinline__ u64 pack2(float lo, float hi) {
    u64 r; asm("mov.b64 %0, {%1, %2};" : "=l"(r) : "f"(lo), "f"(hi)); return r;
}
__device__ __forceinline__ u64 fma2(u64 a, u64 b, u64 c) {
    u64 d; asm("fma.rn.f32x2 %0, %1, %2, %3;" : "=l"(d) : "l"(a), "l"(b), "l"(c)); return d;
}
__device__ __forceinline__ u64 add2(u64 a, u64 b) {
    u64 d; asm("add.rn.f32x2 %0, %1, %2;" : "=l"(d) : "l"(a), "l"(b)); return d;
}
__device__ __forceinline__ void unpack2(u64 v, float& lo, float& hi) {
    asm("mov.b64 {%0, %1}, %2;" : "=f"(lo), "=f"(hi) : "l"(v));
}
__device__ __forceinline__ float sigmoid_f(float x) {
    return __fdividef(1.f, 1.f + __expf(-x));
}
__device__ __forceinline__ float tanh_f(float x) {
    float ax = fabsf(x);
    float e = __expf(-2.f * ax);
    float r = __fdividef(1.f - e, 1.f + e);
    return copysignf(r, x);
}

// One LSTM cell step. Weights in registers; h exchanged via per-warp smem
// as pre-duplicated (h,h) pairs -> LDS.128 yields two FFMA2 multiplicands
// with zero packing MOVs. Double-buffered on step parity: 1 syncwarp/step.
__device__ __forceinline__ void cell_step(float x,
                                          const u64 (&wif)[32], const u64 (&wgo)[32],
                                          u64 wxif, u64 wxgo, u64 bif, u64 bgo,
                                          const u64* __restrict__ hread,
                                          u64* __restrict__ hwrite,
                                          float& h, float& c, int lane)
{
    __syncwarp();                      // all lanes' previous STS visible
    u64 xs = pack2(x, x);
    u64 aif[4], ago[4];
    aif[0] = fma2(xs, wxif, bif);  aif[1] = 0; aif[2] = 0; aif[3] = 0;
    ago[0] = fma2(xs, wxgo, bgo);  ago[1] = 0; ago[2] = 0; ago[3] = 0;
    const ulonglong2* hp = (const ulonglong2*)hread;
    #pragma unroll
    for (int m = 0; m < 16; m++) {
        ulonglong2 v = hp[m];          // ((h2m,h2m),(h2m+1,h2m+1)) broadcast LDS.128
        const int i0 = (2 * m) & 3, i1 = (2 * m + 1) & 3;
        aif[i0] = fma2(v.x, wif[2 * m],     aif[i0]);
        ago[i0] = fma2(v.x, wgo[2 * m],     ago[i0]);
        aif[i1] = fma2(v.y, wif[2 * m + 1], aif[i1]);
        ago[i1] = fma2(v.y, wgo[2 * m + 1], ago[i1]);
    }
    u64 zif = add2(add2(aif[0], aif[1]), add2(aif[2], aif[3]));
    u64 zgo = add2(add2(ago[0], ago[1]), add2(ago[2], ago[3]));

    float zi, zf, zg, zo;
    unpack2(zif, zi, zf);
    unpack2(zgo, zg, zo);
    float ig = sigmoid_f(zi);
    float fg = sigmoid_f(zf);
    float gg = tanh_f(zg);
    float og = sigmoid_f(zo);
    c = fmaf(fg, c, ig * gg);
    h = og * tanh_f(c);
    hwrite[lane] = pack2(h, h);        // STS.64 into the other slot
}

__device__ __forceinline__ float warp_proj(float h, float wo, float bo) {
    float v = h * wo;
    v += __shfl_xor_sync(0xffffffffu, v, 16);
    v += __shfl_xor_sync(0xffffffffu, v, 8);
    v += __shfl_xor_sync(0xffffffffu, v, 4);
    v += __shfl_xor_sync(0xffffffffu, v, 2);
    v += __shfl_xor_sync(0xffffffffu, v, 1);
    return v + bo;
}

__global__ void __launch_bounds__(NTHREADS, 3)
feedback_lstm_kernel(const float* __restrict__ X,
                     const float* __restrict__ Wkw, const float* __restrict__ Ukw,
                     const float* __restrict__ bw,
                     const float* __restrict__ Wkd, const float* __restrict__ Ukd,
                     const float* __restrict__ bdv,
                     const float* __restrict__ Wd,  const float* __restrict__ bd,
                     float* __restrict__ out)
{
    __shared__ float sU0[32 * 128];
    __shared__ float sU1[32 * 128];
    __shared__ float sWx0[128], sWx1[128], sB0[128], sB1[128];
    __shared__ float sWo[UNITS];
    __shared__ float sbo;
    __shared__ __align__(16) u64 hbuf[2][NTHREADS / 32][32];  // double-buffered (h,h)

    const int tid = threadIdx.x;
    #pragma unroll 4
    for (int i = tid; i < 32 * 128; i += NTHREADS) {
        sU0[i] = Ukw[i];
        sU1[i] = Ukd[i];
    }
    if (tid < 128) {
        sWx0[tid] = Wkw[tid];
        sB0[tid]  = bw[tid];
        sWx1[tid] = Wkd[tid];
        sB1[tid]  = bdv[tid];
    }
    if (tid < UNITS) sWo[tid] = Wd[tid];
    if (tid == 0) sbo = bd[0];
    __syncthreads();

    const int lane = tid & 31;
    const int warp = tid >> 5;
    const int b = blockIdx.x * (NTHREADS / 32) + warp;

    // Pre-load this batch's 48 inputs into lane registers (coalesced),
    // redistributed by shfl inside the warmup loop.
    const float* xrow = X + (size_t)b * T_WARM;
    float xa = xrow[lane];
    float xb = (lane < 16) ? xrow[32 + lane] : 0.f;

    const float wo = sWo[lane];
    const float bo = sbo;

    float h = 0.f, c = 0.f;
    hbuf[0][warp][lane] = 0ull;        // h0 = 0, pre-duplicated pair
    int par = 0;

    // ---- Phase 1: warmup (48 steps), warm weights in registers ----
    u64 wif[32], wgo[32];
    u64 wxif, wxgo, bif, bgo;
    #pragma unroll
    for (int k = 0; k < 32; k++) {
        wif[k] = pack2(sU0[k * 128 + lane],      sU0[k * 128 + 32 + lane]);
        wgo[k] = pack2(sU0[k * 128 + 64 + lane], sU0[k * 128 + 96 + lane]);
    }
    wxif = pack2(sWx0[lane],      sWx0[32 + lane]);
    wxgo = pack2(sWx0[64 + lane], sWx0[96 + lane]);
    bif  = pack2(sB0[lane],       sB0[32 + lane]);
    bgo  = pack2(sB0[64 + lane],  sB0[96 + lane]);

    for (int t = 0; t < T_WARM; t++) {
        float x = __shfl_sync(0xffffffffu, (t < 32) ? xa : xb, t & 31);
        cell_step(x, wif, wgo, wxif, wxgo, bif, bgo,
                  hbuf[par][warp], hbuf[par ^ 1][warp], h, c, lane);
        par ^= 1;
    }

    float p = warp_proj(h, wo, bo);
    float myp = p;   // lane 0 keeps step 0; others overwritten at their step

    // ---- Phase 2: decode (23 steps), reload registers with decode weights ----
    #pragma unroll
    for (int k = 0; k < 32; k++) {
        wif[k] = pack2(sU1[k * 128 + lane],      sU1[k * 128 + 32 + lane]);
        wgo[k] = pack2(sU1[k * 128 + 64 + lane], sU1[k * 128 + 96 + lane]);
    }
    wxif = pack2(sWx1[lane],      sWx1[32 + lane]);
    wxgo = pack2(sWx1[64 + lane], sWx1[96 + lane]);
    bif  = pack2(sB1[lane],       sB1[32 + lane]);
    bgo  = pack2(sB1[64 + lane],  sB1[96 + lane]);

    for (int s = 1; s < OUT_STEPS; s++) {
        cell_step(p, wif, wgo, wxif, wxgo, bif, bgo,
                  hbuf[par][warp], hbuf[par ^ 1][warp], h, c, lane);
        par ^= 1;
        p = warp_proj(h, wo, bo);
        if (lane == s) myp = p;
    }

    if (lane < OUT_STEPS) out[(size_t)b * OUT_STEPS + lane] = myp;
}

extern "C" void kernel_launch(void* const* d_in, const int* in_sizes, int n_in,
                              void* d_out, int out_size) {
    const float* X   = (const float*)d_in[0];
    const float* Wkw = (const float*)d_in[1];
    const float* Ukw = (const float*)d_in[2];
    const float* bw  = (const float*)d_in[3];
    const float* Wkd = (const float*)d_in[4];
    const float* Ukd = (const float*)d_in[5];
    const float* bdv = (const float*)d_in[6];
    const float* Wd  = (const float*)d_in[7];
    const float* bd  = (const float*)d_in[8];
    float* out = (float*)d_out;

    int Bn = in_sizes[0] / T_WARM;            // F == 1
    int batches_per_block = NTHREADS / 32;
    int grid = (Bn + batches_per_block - 1) / batches_per_block;
    feedback_lstm_kernel<<<grid, NTHREADS>>>(X, Wkw, Ukw, bw, Wkd, Ukd, bdv, Wd, bd, out);
}

// round 8
// speedup vs baseline: 1.1873x; 1.1873x over previous
#include <cuda_runtime.h>

#define T_WARM 48
#define OUT_STEPS 24
#define UNITS 32
#define NTHREADS 128          // 4 warps
#define WARPS (NTHREADS / 32)
#define BPW 2                 // batch elements per warp
#define BPB (WARPS * BPW)     // 8 batches per block

typedef unsigned long long u64;

__device__ __forceinline__ u64 pack2(float lo, float hi) {
    u64 r; asm("mov.b64 %0, {%1, %2};" : "=l"(r) : "f"(lo), "f"(hi)); return r;
}
__device__ __forceinline__ u64 fma2(u64 a, u64 b, u64 c) {
    u64 d; asm("fma.rn.f32x2 %0, %1, %2, %3;" : "=l"(d) : "l"(a), "l"(b), "l"(c)); return d;
}
__device__ __forceinline__ void unpack2(u64 v, float& lo, float& hi) {
    asm("mov.b64 {%0, %1}, %2;" : "=f"(lo), "=f"(hi) : "l"(v));
}
__device__ __forceinline__ float sigmoid_f(float x) {
    return __fdividef(1.f, 1.f + __expf(-x));
}
__device__ __forceinline__ float tanh_f(float x) {
    float ax = fabsf(x);
    float e = __expf(-2.f * ax);
    float r = __fdividef(1.f - e, 1.f + e);
    return copysignf(r, x);
}

__device__ __forceinline__ void activ(u64 zif, u64 zgo, float& h, float& c) {
    float zi, zf, zg, zo;
    unpack2(zif, zi, zf);
    unpack2(zgo, zg, zo);
    float ig = sigmoid_f(zi);
    float fg = sigmoid_f(zf);
    float gg = tanh_f(zg);
    float og = sigmoid_f(zo);
    c = fmaf(fg, c, ig * gg);
    h = og * tanh_f(c);
}

// One step for BOTH batch elements of this warp. Weights in registers
// (shared across the two batches); h exchanged via per-warp smem as
// pre-duplicated (h,h) pairs -> LDS.128 yields two FFMA2 multiplicands.
// Double-buffered on parity: exactly one __syncwarp per step.
__device__ __forceinline__ void step2(float xA, float xB,
                                      const u64 (&wif)[32], const u64 (&wgo)[32],
                                      u64 wxif, u64 wxgo, u64 bif, u64 bgo,
                                      const u64* __restrict__ hrA,
                                      const u64* __restrict__ hrB,
                                      u64* __restrict__ hwA,
                                      u64* __restrict__ hwB,
                                      float& hA, float& cA,
                                      float& hB, float& cB, int lane)
{
    __syncwarp();                       // previous step's STS visible
    u64 xsA = pack2(xA, xA), xsB = pack2(xB, xB);
    u64 aifA = fma2(xsA, wxif, bif), agoA = fma2(xsA, wxgo, bgo);
    u64 aifB = fma2(xsB, wxif, bif), agoB = fma2(xsB, wxgo, bgo);
    const ulonglong2* hpA = (const ulonglong2*)hrA;
    const ulonglong2* hpB = (const ulonglong2*)hrB;
    #pragma unroll
    for (int m = 0; m < 16; m++) {
        ulonglong2 vA = hpA[m];         // ((h2m,h2m),(h2m+1,h2m+1)) broadcast
        ulonglong2 vB = hpB[m];
        aifA = fma2(vA.x, wif[2*m],   aifA);
        agoA = fma2(vA.x, wgo[2*m],   agoA);
        aifA = fma2(vA.y, wif[2*m+1], aifA);
        agoA = fma2(vA.y, wgo[2*m+1], agoA);
        aifB = fma2(vB.x, wif[2*m],   aifB);
        agoB = fma2(vB.x, wgo[2*m],   agoB);
        aifB = fma2(vB.y, wif[2*m+1], aifB);
        agoB = fma2(vB.y, wgo[2*m+1], agoB);
    }
    activ(aifA, agoA, hA, cA);
    activ(aifB, agoB, hB, cB);
    hwA[lane] = pack2(hA, hA);          // STS.64 into the other parity slot
    hwB[lane] = pack2(hB, hB);
}

__device__ __forceinline__ float warp_proj(float h, float wo, float bo) {
    float v = h * wo;
    v += __shfl_xor_sync(0xffffffffu, v, 16);
    v += __shfl_xor_sync(0xffffffffu, v, 8);
    v += __shfl_xor_sync(0xffffffffu, v, 4);
    v += __shfl_xor_sync(0xffffffffu, v, 2);
    v += __shfl_xor_sync(0xffffffffu, v, 1);
    return v + bo;
}

__global__ void __launch_bounds__(NTHREADS, 3)
feedback_lstm_kernel(const float* __restrict__ X,
                     const float* __restrict__ Wkw, const float* __restrict__ Ukw,
                     const float* __restrict__ bw,
                     const float* __restrict__ Wkd, const float* __restrict__ Ukd,
                     const float* __restrict__ bdv,
                     const float* __restrict__ Wd,  const float* __restrict__ bd,
                     float* __restrict__ out)
{
    __shared__ float sU0[32 * 128];
    __shared__ float sU1[32 * 128];
    __shared__ float sWx0[128], sWx1[128], sB0[128], sB1[128];
    __shared__ float sWo[UNITS];
    __shared__ float sbo;
    __shared__ __align__(16) u64 hbuf[2][WARPS][BPW][32];   // (h,h) pairs
    __shared__ float sX[BPB][T_WARM];

    const int tid = threadIdx.x;
    #pragma unroll 4
    for (int i = tid; i < 32 * 128; i += NTHREADS) {
        sU0[i] = Ukw[i];
        sU1[i] = Ukd[i];
    }
    if (tid < 128) {
        sWx0[tid] = Wkw[tid];
        sB0[tid]  = bw[tid];
        sWx1[tid] = Wkd[tid];
        sB1[tid]  = bdv[tid];
    }
    if (tid < UNITS) sWo[tid] = Wd[tid];
    if (tid == 0) sbo = bd[0];

    // Stage this block's 8 input rows (coalesced).
    const size_t base = (size_t)blockIdx.x * BPB;
    for (int i = tid; i < BPB * T_WARM; i += NTHREADS) {
        int bb = i / T_WARM, t = i % T_WARM;
        sX[bb][t] = X[base * T_WARM + (size_t)bb * T_WARM + t];
    }
    __syncthreads();

    const int lane = tid & 31;
    const int warp = tid >> 5;
    const float wo = sWo[lane];
    const float bo = sbo;

    float hA = 0.f, cA = 0.f, hB = 0.f, cB = 0.f;
    hbuf[0][warp][0][lane] = 0ull;
    hbuf[0][warp][1][lane] = 0ull;
    int par = 0;

    // ---- Phase 1: warmup, warm weights in registers ----
    u64 wif[32], wgo[32];
    u64 wxif, wxgo, bif, bgo;
    #pragma unroll
    for (int k = 0; k < 32; k++) {
        wif[k] = pack2(sU0[k * 128 + lane],      sU0[k * 128 + 32 + lane]);
        wgo[k] = pack2(sU0[k * 128 + 64 + lane], sU0[k * 128 + 96 + lane]);
    }
    wxif = pack2(sWx0[lane],      sWx0[32 + lane]);
    wxgo = pack2(sWx0[64 + lane], sWx0[96 + lane]);
    bif  = pack2(sB0[lane],       sB0[32 + lane]);
    bgo  = pack2(sB0[64 + lane],  sB0[96 + lane]);

    for (int t = 0; t < T_WARM; t++) {
        float xA = sX[2 * warp][t];
        float xB = sX[2 * warp + 1][t];
        step2(xA, xB, wif, wgo, wxif, wxgo, bif, bgo,
              hbuf[par][warp][0], hbuf[par][warp][1],
              hbuf[par ^ 1][warp][0], hbuf[par ^ 1][warp][1],
              hA, cA, hB, cB, lane);
        par ^= 1;
    }

    float pA = warp_proj(hA, wo, bo);
    float pB = warp_proj(hB, wo, bo);
    float mypA = pA, mypB = pB;

    // ---- Phase 2: decode, reload registers with decode weights ----
    #pragma unroll
    for (int k = 0; k < 32; k++) {
        wif[k] = pack2(sU1[k * 128 + lane],      sU1[k * 128 + 32 + lane]);
        wgo[k] = pack2(sU1[k * 128 + 64 + lane], sU1[k * 128 + 96 + lane]);
    }
    wxif = pack2(sWx1[lane],      sWx1[32 + lane]);
    wxgo = pack2(sWx1[64 + lane], sWx1[96 + lane]);
    bif  = pack2(sB1[lane],       sB1[32 + lane]);
    bgo  = pack2(sB1[64 + lane],  sB1[96 + lane]);

    for (int s = 1; s < OUT_STEPS; s++) {
        step2(pA, pB, wif, wgo, wxif, wxgo, bif, bgo,
              hbuf[par][warp][0], hbuf[par][warp][1],
              hbuf[par ^ 1][warp][0], hbuf[par ^ 1][warp][1],
              hA, cA, hB, cB, lane);
        par ^= 1;
        pA = warp_proj(hA, wo, bo);
        pB = warp_proj(hB, wo, bo);
        if (lane == s) { mypA = pA; mypB = pB; }
    }

    if (lane < OUT_STEPS) {
        out[(base + 2 * warp)     * OUT_STEPS + lane] = mypA;
        out[(base + 2 * warp + 1) * OUT_STEPS + lane] = mypB;
    }
}

extern "C" void kernel_launch(void* const* d_in, const int* in_sizes, int n_in,
                              void* d_out, int out_size) {
    const float* X   = (const float*)d_in[0];
    const float* Wkw = (const float*)d_in[1];
    const float* Ukw = (const float*)d_in[2];
    const float* bw  = (const float*)d_in[3];
    const float* Wkd = (const float*)d_in[4];
    const float* Ukd = (const float*)d_in[5];
    const float* bdv = (const float*)d_in[6];
    const float* Wd  = (const float*)d_in[7];
    const float* bd  = (const float*)d_in[8];
    float* out = (float*)d_out;

    int Bn = in_sizes[0] / T_WARM;            // F == 1
    int grid = (Bn + BPB - 1) / BPB;
    feedback_lstm_kernel<<<grid, NTHREADS>>>(X, Wkw, Ukw, bw, Wkd, Ukd, bdv, Wd, bd, out);
}

// round 9
// speedup vs baseline: 1.2542x; 1.0564x over previous
#include <cuda_runtime.h>

#define T_WARM 48
#define OUT_STEPS 24
#define UNITS 32
#define NTHREADS 128          // 4 warps
#define WARPS (NTHREADS / 32)
#define BPW 2                 // batch elements per warp
#define BPB (WARPS * BPW)     // 8 batches per block

typedef unsigned long long u64;

__device__ __forceinline__ u64 pack2(float lo, float hi) {
    u64 r; asm("mov.b64 %0, {%1, %2};" : "=l"(r) : "f"(lo), "f"(hi)); return r;
}
__device__ __forceinline__ u64 fma2(u64 a, u64 b, u64 c) {
    u64 d; asm("fma.rn.f32x2 %0, %1, %2, %3;" : "=l"(d) : "l"(a), "l"(b), "l"(c)); return d;
}
__device__ __forceinline__ float hadd2(u64 v) {
    float lo, hi; asm("mov.b64 {%0, %1}, %2;" : "=f"(lo), "=f"(hi) : "l"(v));
    return lo + hi;
}
__device__ __forceinline__ float sigmoid_f(float x) {
    return __fdividef(1.f, 1.f + __expf(-x));
}
__device__ __forceinline__ float tanh_f(float x) {
    float ax = fabsf(x);
    float e = __expf(-2.f * ax);
    float r = __fdividef(1.f - e, 1.f + e);
    return copysignf(r, x);
}

// k-paired accumulation: acc.lo sums even-k terms, acc.hi odd-k terms.
// h lives in smem as plain floats; one LDS.128 = 4 h values = 2 multiplicand
// pairs. Horizontal add once per gate at the end.
__device__ __forceinline__ void step2(float xA, float xB,
                                      const u64 (&wi)[16], const u64 (&wf)[16],
                                      const u64 (&wg)[16], const u64 (&wq)[16],
                                      float wxi, float wxf, float wxg, float wxo,
                                      float bi,  float bf,  float bg,  float bo_,
                                      const float* __restrict__ hrA,
                                      const float* __restrict__ hrB,
                                      float* __restrict__ hwA,
                                      float* __restrict__ hwB,
                                      float& hA, float& cA,
                                      float& hB, float& cB, int lane)
{
    __syncwarp();                       // previous step's STS visible
    u64 aiA = 0, afA = 0, agA = 0, aoA = 0;
    u64 aiB = 0, afB = 0, agB = 0, aoB = 0;
    const ulonglong2* hpA = (const ulonglong2*)hrA;   // (h0,h1),(h2,h3) per 16B
    const ulonglong2* hpB = (const ulonglong2*)hrB;
    #pragma unroll
    for (int q = 0; q < 8; q++) {
        ulonglong2 vA = hpA[q];         // broadcast LDS.128: 4 h values
        ulonglong2 vB = hpB[q];
        aiA = fma2(vA.x, wi[2*q], aiA);  aiA = fma2(vA.y, wi[2*q+1], aiA);
        afA = fma2(vA.x, wf[2*q], afA);  afA = fma2(vA.y, wf[2*q+1], afA);
        agA = fma2(vA.x, wg[2*q], agA);  agA = fma2(vA.y, wg[2*q+1], agA);
        aoA = fma2(vA.x, wq[2*q], aoA);  aoA = fma2(vA.y, wq[2*q+1], aoA);
        aiB = fma2(vB.x, wi[2*q], aiB);  aiB = fma2(vB.y, wi[2*q+1], aiB);
        afB = fma2(vB.x, wf[2*q], afB);  afB = fma2(vB.y, wf[2*q+1], afB);
        agB = fma2(vB.x, wg[2*q], agB);  agB = fma2(vB.y, wg[2*q+1], agB);
        aoB = fma2(vB.x, wq[2*q], aoB);  aoB = fma2(vB.y, wq[2*q+1], aoB);
    }
    {
        float zi = hadd2(aiA) + fmaf(xA, wxi, bi);
        float zf = hadd2(afA) + fmaf(xA, wxf, bf);
        float zg = hadd2(agA) + fmaf(xA, wxg, bg);
        float zo = hadd2(aoA) + fmaf(xA, wxo, bo_);
        float ig = sigmoid_f(zi), fg = sigmoid_f(zf);
        float gg = tanh_f(zg),   og = sigmoid_f(zo);
        cA = fmaf(fg, cA, ig * gg);
        hA = og * tanh_f(cA);
    }
    {
        float zi = hadd2(aiB) + fmaf(xB, wxi, bi);
        float zf = hadd2(afB) + fmaf(xB, wxf, bf);
        float zg = hadd2(agB) + fmaf(xB, wxg, bg);
        float zo = hadd2(aoB) + fmaf(xB, wxo, bo_);
        float ig = sigmoid_f(zi), fg = sigmoid_f(zf);
        float gg = tanh_f(zg),   og = sigmoid_f(zo);
        cB = fmaf(fg, cB, ig * gg);
        hB = og * tanh_f(cB);
    }
    hwA[lane] = hA;                     // STS.32 into the other parity slot
    hwB[lane] = hB;
}

__device__ __forceinline__ float warp_proj(float h, float wo, float bo) {
    float v = h * wo;
    v += __shfl_xor_sync(0xffffffffu, v, 16);
    v += __shfl_xor_sync(0xffffffffu, v, 8);
    v += __shfl_xor_sync(0xffffffffu, v, 4);
    v += __shfl_xor_sync(0xffffffffu, v, 2);
    v += __shfl_xor_sync(0xffffffffu, v, 1);
    return v + bo;
}

__global__ void __launch_bounds__(NTHREADS, 3)
feedback_lstm_kernel(const float* __restrict__ X,
                     const float* __restrict__ Wkw, const float* __restrict__ Ukw,
                     const float* __restrict__ bw,
                     const float* __restrict__ Wkd, const float* __restrict__ Ukd,
                     const float* __restrict__ bdv,
                     const float* __restrict__ Wd,  const float* __restrict__ bd,
                     float* __restrict__ out)
{
    __shared__ float sU0[32 * 128];
    __shared__ float sU1[32 * 128];
    __shared__ float sWx0[128], sWx1[128], sB0[128], sB1[128];
    __shared__ float sWo[UNITS];
    __shared__ float sbo;
    __shared__ __align__(16) float hbuf[2][WARPS][BPW][32];  // plain h values
    __shared__ float sX[BPB][T_WARM];

    const int tid = threadIdx.x;
    #pragma unroll 4
    for (int i = tid; i < 32 * 128; i += NTHREADS) {
        sU0[i] = Ukw[i];
        sU1[i] = Ukd[i];
    }
    if (tid < 128) {
        sWx0[tid] = Wkw[tid];
        sB0[tid]  = bw[tid];
        sWx1[tid] = Wkd[tid];
        sB1[tid]  = bdv[tid];
    }
    if (tid < UNITS) sWo[tid] = Wd[tid];
    if (tid == 0) sbo = bd[0];

    // Stage this block's 8 input rows (coalesced).
    const size_t base = (size_t)blockIdx.x * BPB;
    for (int i = tid; i < BPB * T_WARM; i += NTHREADS) {
        int bb = i / T_WARM, t = i % T_WARM;
        sX[bb][t] = X[base * T_WARM + (size_t)bb * T_WARM + t];
    }
    __syncthreads();

    const int lane = tid & 31;
    const int warp = tid >> 5;
    const float wo = sWo[lane];
    const float bo = sbo;

    float hA = 0.f, cA = 0.f, hB = 0.f, cB = 0.f;
    hbuf[0][warp][0][lane] = 0.f;
    hbuf[0][warp][1][lane] = 0.f;
    int par = 0;

    // ---- Phase 1: warmup, warm weights in registers ----
    // wi[m] = (U[2m][j], U[2m+1][j]) for this lane's unit j, per gate.
    u64 wi[16], wf[16], wg[16], wq[16];
    float wxi, wxf, wxg, wxo, bi, bf, bg, bo_;
    #pragma unroll
    for (int m = 0; m < 16; m++) {
        wi[m] = pack2(sU0[(2*m) * 128 + lane],       sU0[(2*m+1) * 128 + lane]);
        wf[m] = pack2(sU0[(2*m) * 128 + 32 + lane],  sU0[(2*m+1) * 128 + 32 + lane]);
        wg[m] = pack2(sU0[(2*m) * 128 + 64 + lane],  sU0[(2*m+1) * 128 + 64 + lane]);
        wq[m] = pack2(sU0[(2*m) * 128 + 96 + lane],  sU0[(2*m+1) * 128 + 96 + lane]);
    }
    wxi = sWx0[lane]; wxf = sWx0[32 + lane]; wxg = sWx0[64 + lane]; wxo = sWx0[96 + lane];
    bi  = sB0[lane];  bf  = sB0[32 + lane];  bg  = sB0[64 + lane];  bo_ = sB0[96 + lane];

    for (int t = 0; t < T_WARM; t++) {
        float xA = sX[2 * warp][t];
        float xB = sX[2 * warp + 1][t];
        step2(xA, xB, wi, wf, wg, wq, wxi, wxf, wxg, wxo, bi, bf, bg, bo_,
              hbuf[par][warp][0], hbuf[par][warp][1],
              hbuf[par ^ 1][warp][0], hbuf[par ^ 1][warp][1],
              hA, cA, hB, cB, lane);
        par ^= 1;
    }

    float pA = warp_proj(hA, wo, bo);
    float pB = warp_proj(hB, wo, bo);
    float mypA = pA, mypB = pB;

    // ---- Phase 2: decode, reload registers with decode weights ----
    #pragma unroll
    for (int m = 0; m < 16; m++) {
        wi[m] = pack2(sU1[(2*m) * 128 + lane],       sU1[(2*m+1) * 128 + lane]);
        wf[m] = pack2(sU1[(2*m) * 128 + 32 + lane],  sU1[(2*m+1) * 128 + 32 + lane]);
        wg[m] = pack2(sU1[(2*m) * 128 + 64 + lane],  sU1[(2*m+1) * 128 + 64 + lane]);
        wq[m] = pack2(sU1[(2*m) * 128 + 96 + lane],  sU1[(2*m+1) * 128 + 96 + lane]);
    }
    wxi = sWx1[lane]; wxf = sWx1[32 + lane]; wxg = sWx1[64 + lane]; wxo = sWx1[96 + lane];
    bi  = sB1[lane];  bf  = sB1[32 + lane];  bg  = sB1[64 + lane];  bo_ = sB1[96 + lane];

    for (int s = 1; s < OUT_STEPS; s++) {
        step2(pA, pB, wi, wf, wg, wq, wxi, wxf, wxg, wxo, bi, bf, bg, bo_,
              hbuf[par][warp][0], hbuf[par][warp][1],
              hbuf[par ^ 1][warp][0], hbuf[par ^ 1][warp][1],
              hA, cA, hB, cB, lane);
        par ^= 1;
        pA = warp_proj(hA, wo, bo);
        pB = warp_proj(hB, wo, bo);
        if (lane == s) { mypA = pA; mypB = pB; }
    }

    if (lane < OUT_STEPS) {
        out[(base + 2 * warp)     * OUT_STEPS + lane] = mypA;
        out[(base + 2 * warp + 1) * OUT_STEPS + lane] = mypB;
    }
}

extern "C" void kernel_launch(void* const* d_in, const int* in_sizes, int n_in,
                              void* d_out, int out_size) {
    const float* X   = (const float*)d_in[0];
    const float* Wkw = (const float*)d_in[1];
    const float* Ukw = (const float*)d_in[2];
    const float* bw  = (const float*)d_in[3];
    const float* Wkd = (const float*)d_in[4];
    const float* Ukd = (const float*)d_in[5];
    const float* bdv = (const float*)d_in[6];
    const float* Wd  = (const float*)d_in[7];
    const float* bd  = (const float*)d_in[8];
    float* out = (float*)d_out;

    int Bn = in_sizes[0] / T_WARM;            // F == 1
    int grid = (Bn + BPB - 1) / BPB;
    feedback_lstm_kernel<<<grid, NTHREADS>>>(X, Wkw, Ukw, bw, Wkd, Ukd, bdv, Wd, bd, out);
}

// round 10
// speedup vs baseline: 1.4236x; 1.1351x over previous
#include <cuda_runtime.h>

#define T_WARM 48
#define OUT_STEPS 24
#define UNITS 32
#define NTHREADS 128          // 4 warps
#define WARPS (NTHREADS / 32)
#define BPW 2                 // batch elements per warp
#define BPB (WARPS * BPW)     // 8 batches per block

typedef unsigned long long u64;

__device__ __forceinline__ u64 pack2(float lo, float hi) {
    u64 r; asm("mov.b64 %0, {%1, %2};" : "=l"(r) : "f"(lo), "f"(hi)); return r;
}
__device__ __forceinline__ u64 fma2(u64 a, u64 b, u64 c) {
    u64 d; asm("fma.rn.f32x2 %0, %1, %2, %3;" : "=l"(d) : "l"(a), "l"(b), "l"(c)); return d;
}
__device__ __forceinline__ float hadd2(u64 v) {
    float lo, hi; asm("mov.b64 {%0, %1}, %2;" : "=f"(lo), "=f"(hi) : "l"(v));
    return lo + hi;
}
// Hardware tanh (MUFU.TANH, sm_75+): 1 op vs ~6-op expf chain.
__device__ __forceinline__ float tanh_hw(float x) {
    float r; asm("tanh.approx.f32 %0, %1;" : "=f"(r) : "f"(x)); return r;
}
__device__ __forceinline__ float sigmoid_hw(float x) {
    return fmaf(0.5f, tanh_hw(0.5f * x), 0.5f);
}

// k-paired accumulation: acc.lo sums even-k terms, acc.hi odd-k terms.
// h lives in smem as plain floats; one LDS.128 = 4 h values = 2 multiplicand
// pairs. Horizontal add once per gate at the end. Activations via MUFU.TANH.
__device__ __forceinline__ void step2(float xA, float xB,
                                      const u64 (&wi)[16], const u64 (&wf)[16],
                                      const u64 (&wg)[16], const u64 (&wq)[16],
                                      float wxi, float wxf, float wxg, float wxo,
                                      float bi,  float bf,  float bg,  float bo_,
                                      const float* __restrict__ hrA,
                                      const float* __restrict__ hrB,
                                      float* __restrict__ hwA,
                                      float* __restrict__ hwB,
                                      float& hA, float& cA,
                                      float& hB, float& cB, int lane)
{
    __syncwarp();                       // previous step's STS visible
    u64 aiA = 0, afA = 0, agA = 0, aoA = 0;
    u64 aiB = 0, afB = 0, agB = 0, aoB = 0;
    const ulonglong2* hpA = (const ulonglong2*)hrA;   // (h0,h1),(h2,h3) per 16B
    const ulonglong2* hpB = (const ulonglong2*)hrB;
    #pragma unroll
    for (int q = 0; q < 8; q++) {
        ulonglong2 vA = hpA[q];         // broadcast LDS.128: 4 h values
        ulonglong2 vB = hpB[q];
        aiA = fma2(vA.x, wi[2*q], aiA);  aiA = fma2(vA.y, wi[2*q+1], aiA);
        afA = fma2(vA.x, wf[2*q], afA);  afA = fma2(vA.y, wf[2*q+1], afA);
        agA = fma2(vA.x, wg[2*q], agA);  agA = fma2(vA.y, wg[2*q+1], agA);
        aoA = fma2(vA.x, wq[2*q], aoA);  aoA = fma2(vA.y, wq[2*q+1], aoA);
        aiB = fma2(vB.x, wi[2*q], aiB);  aiB = fma2(vB.y, wi[2*q+1], aiB);
        afB = fma2(vB.x, wf[2*q], afB);  afB = fma2(vB.y, wf[2*q+1], afB);
        agB = fma2(vB.x, wg[2*q], agB);  agB = fma2(vB.y, wg[2*q+1], agB);
        aoB = fma2(vB.x, wq[2*q], aoB);  aoB = fma2(vB.y, wq[2*q+1], aoB);
    }
    {
        float zi = hadd2(aiA) + fmaf(xA, wxi, bi);
        float zf = hadd2(afA) + fmaf(xA, wxf, bf);
        float zg = hadd2(agA) + fmaf(xA, wxg, bg);
        float zo = hadd2(aoA) + fmaf(xA, wxo, bo_);
        float ig = sigmoid_hw(zi), fg = sigmoid_hw(zf);
        float gg = tanh_hw(zg),    og = sigmoid_hw(zo);
        cA = fmaf(fg, cA, ig * gg);
        hA = og * tanh_hw(cA);
    }
    {
        float zi = hadd2(aiB) + fmaf(xB, wxi, bi);
        float zf = hadd2(afB) + fmaf(xB, wxf, bf);
        float zg = hadd2(agB) + fmaf(xB, wxg, bg);
        float zo = hadd2(aoB) + fmaf(xB, wxo, bo_);
        float ig = sigmoid_hw(zi), fg = sigmoid_hw(zf);
        float gg = tanh_hw(zg),    og = sigmoid_hw(zo);
        cB = fmaf(fg, cB, ig * gg);
        hB = og * tanh_hw(cB);
    }
    hwA[lane] = hA;                     // STS.32 into the other parity slot
    hwB[lane] = hB;
}

__device__ __forceinline__ float warp_proj(float h, float wo, float bo) {
    float v = h * wo;
    v += __shfl_xor_sync(0xffffffffu, v, 16);
    v += __shfl_xor_sync(0xffffffffu, v, 8);
    v += __shfl_xor_sync(0xffffffffu, v, 4);
    v += __shfl_xor_sync(0xffffffffu, v, 2);
    v += __shfl_xor_sync(0xffffffffu, v, 1);
    return v + bo;
}

__global__ void __launch_bounds__(NTHREADS, 3)
feedback_lstm_kernel(const float* __restrict__ X,
                     const float* __restrict__ Wkw, const float* __restrict__ Ukw,
                     const float* __restrict__ bw,
                     const float* __restrict__ Wkd, const float* __restrict__ Ukd,
                     const float* __restrict__ bdv,
                     const float* __restrict__ Wd,  const float* __restrict__ bd,
                     float* __restrict__ out)
{
    __shared__ float sU0[32 * 128];
    __shared__ float sU1[32 * 128];
    __shared__ float sWx0[128], sWx1[128], sB0[128], sB1[128];
    __shared__ float sWo[UNITS];
    __shared__ float sbo;
    __shared__ __align__(16) float hbuf[2][WARPS][BPW][32];  // plain h values
    __shared__ float sX[BPB][T_WARM];

    const int tid = threadIdx.x;
    #pragma unroll 4
    for (int i = tid; i < 32 * 128; i += NTHREADS) {
        sU0[i] = Ukw[i];
        sU1[i] = Ukd[i];
    }
    if (tid < 128) {
        sWx0[tid] = Wkw[tid];
        sB0[tid]  = bw[tid];
        sWx1[tid] = Wkd[tid];
        sB1[tid]  = bdv[tid];
    }
    if (tid < UNITS) sWo[tid] = Wd[tid];
    if (tid == 0) sbo = bd[0];

    // Stage this block's 8 input rows (coalesced).
    const size_t base = (size_t)blockIdx.x * BPB;
    for (int i = tid; i < BPB * T_WARM; i += NTHREADS) {
        int bb = i / T_WARM, t = i % T_WARM;
        sX[bb][t] = X[base * T_WARM + (size_t)bb * T_WARM + t];
    }
    __syncthreads();

    const int lane = tid & 31;
    const int warp = tid >> 5;
    const float wo = sWo[lane];
    const float bo = sbo;

    float hA = 0.f, cA = 0.f, hB = 0.f, cB = 0.f;
    hbuf[0][warp][0][lane] = 0.f;
    hbuf[0][warp][1][lane] = 0.f;
    int par = 0;

    // ---- Phase 1: warmup, warm weights in registers ----
    // wi[m] = (U[2m][j], U[2m+1][j]) for this lane's unit j, per gate.
    u64 wi[16], wf[16], wg[16], wq[16];
    float wxi, wxf, wxg, wxo, bi, bf, bg, bo_;
    #pragma unroll
    for (int m = 0; m < 16; m++) {
        wi[m] = pack2(sU0[(2*m) * 128 + lane],       sU0[(2*m+1) * 128 + lane]);
        wf[m] = pack2(sU0[(2*m) * 128 + 32 + lane],  sU0[(2*m+1) * 128 + 32 + lane]);
        wg[m] = pack2(sU0[(2*m) * 128 + 64 + lane],  sU0[(2*m+1) * 128 + 64 + lane]);
        wq[m] = pack2(sU0[(2*m) * 128 + 96 + lane],  sU0[(2*m+1) * 128 + 96 + lane]);
    }
    wxi = sWx0[lane]; wxf = sWx0[32 + lane]; wxg = sWx0[64 + lane]; wxo = sWx0[96 + lane];
    bi  = sB0[lane];  bf  = sB0[32 + lane];  bg  = sB0[64 + lane];  bo_ = sB0[96 + lane];

    for (int t = 0; t < T_WARM; t++) {
        float xA = sX[2 * warp][t];
        float xB = sX[2 * warp + 1][t];
        step2(xA, xB, wi, wf, wg, wq, wxi, wxf, wxg, wxo, bi, bf, bg, bo_,
              hbuf[par][warp][0], hbuf[par][warp][1],
              hbuf[par ^ 1][warp][0], hbuf[par ^ 1][warp][1],
              hA, cA, hB, cB, lane);
        par ^= 1;
    }

    float pA = warp_proj(hA, wo, bo);
    float pB = warp_proj(hB, wo, bo);
    float mypA = pA, mypB = pB;

    // ---- Phase 2: decode, reload registers with decode weights ----
    #pragma unroll
    for (int m = 0; m < 16; m++) {
        wi[m] = pack2(sU1[(2*m) * 128 + lane],       sU1[(2*m+1) * 128 + lane]);
        wf[m] = pack2(sU1[(2*m) * 128 + 32 + lane],  sU1[(2*m+1) * 128 + 32 + lane]);
        wg[m] = pack2(sU1[(2*m) * 128 + 64 + lane],  sU1[(2*m+1) * 128 + 64 + lane]);
        wq[m] = pack2(sU1[(2*m) * 128 + 96 + lane],  sU1[(2*m+1) * 128 + 96 + lane]);
    }
    wxi = sWx1[lane]; wxf = sWx1[32 + lane]; wxg = sWx1[64 + lane]; wxo = sWx1[96 + lane];
    bi  = sB1[lane];  bf  = sB1[32 + lane];  bg  = sB1[64 + lane];  bo_ = sB1[96 + lane];

    for (int s = 1; s < OUT_STEPS; s++) {
        step2(pA, pB, wi, wf, wg, wq, wxi, wxf, wxg, wxo, bi, bf, bg, bo_,
              hbuf[par][warp][0], hbuf[par][warp][1],
              hbuf[par ^ 1][warp][0], hbuf[par ^ 1][warp][1],
              hA, cA, hB, cB, lane);
        par ^= 1;
        pA = warp_proj(hA, wo, bo);
        pB = warp_proj(hB, wo, bo);
        if (lane == s) { mypA = pA; mypB = pB; }
    }

    if (lane < OUT_STEPS) {
        out[(base + 2 * warp)     * OUT_STEPS + lane] = mypA;
        out[(base + 2 * warp + 1) * OUT_STEPS + lane] = mypB;
    }
}

extern "C" void kernel_launch(void* const* d_in, const int* in_sizes, int n_in,
                              void* d_out, int out_size) {
    const float* X   = (const float*)d_in[0];
    const float* Wkw = (const float*)d_in[1];
    const float* Ukw = (const float*)d_in[2];
    const float* bw  = (const float*)d_in[3];
    const float* Wkd = (const float*)d_in[4];
    const float* Ukd = (const float*)d_in[5];
    const float* bdv = (const float*)d_in[6];
    const float* Wd  = (const float*)d_in[7];
    const float* bd  = (const float*)d_in[8];
    float* out = (float*)d_out;

    int Bn = in_sizes[0] / T_WARM;            // F == 1
    int grid = (Bn + BPB - 1) / BPB;
    feedback_lstm_kernel<<<grid, NTHREADS>>>(X, Wkw, Ukw, bw, Wkd, Ukd, bdv, Wd, bd, out);
}

// round 13
// speedup vs baseline: 1.5556x; 1.0927x over previous
#include <cuda_runtime.h>

#define T_WARM 48
#define OUT_STEPS 24
#define UNITS 32
#define NTHREADS 128          // 4 warps
#define WARPS (NTHREADS / 32)
#define BPW 4                 // batch elements per warp (ILP)
#define BPB (WARPS * BPW)     // 16 batches per block

typedef unsigned long long u64;

__device__ __forceinline__ u64 pack2(float lo, float hi) {
    u64 r; asm("mov.b64 %0, {%1, %2};" : "=l"(r) : "f"(lo), "f"(hi)); return r;
}
__device__ __forceinline__ u64 fma2(u64 a, u64 b, u64 c) {
    u64 d; asm("fma.rn.f32x2 %0, %1, %2, %3;" : "=l"(d) : "l"(a), "l"(b), "l"(c)); return d;
}
__device__ __forceinline__ float hadd2(u64 v) {
    float lo, hi; asm("mov.b64 {%0, %1}, %2;" : "=f"(lo), "=f"(hi) : "l"(v));
    return lo + hi;
}
// Hardware tanh (MUFU.TANH).
__device__ __forceinline__ float tanh_hw(float x) {
    float r; asm("tanh.approx.f32 %0, %1;" : "=f"(r) : "f"(x)); return r;
}
// Sigmoid with the 0.5 input scaling pre-folded into the weights:
// z' = 0.5*z  ->  sigmoid(z) = 0.5*tanh(z') + 0.5.
__device__ __forceinline__ float sigmoid_pre(float zp) {
    return fmaf(0.5f, tanh_hw(zp), 0.5f);
}

// One step for all BPW batch elements of this warp. Weights in registers,
// shared across batches. h via per-warp smem, one LDS.128 = 4 h values.
// Gate-pair accumulators: acc.lo = even-k sum (+ x/bias folded in),
// acc.hi = odd-k sum; one horizontal add per gate at the end.
__device__ __forceinline__ void stepN(const float (&xin)[BPW],
                                      const u64 (&wi)[16], const u64 (&wf)[16],
                                      const u64 (&wg)[16], const u64 (&wq)[16],
                                      u64 wxi2, u64 wxf2, u64 wxg2, u64 wxo2,
                                      u64 bi2,  u64 bf2,  u64 bg2,  u64 bo2,
                                      const float* (&hr)[BPW], float* (&hw)[BPW],
                                      float (&h)[BPW], float (&c)[BPW], int lane)
{
    __syncwarp();                       // previous step's STS visible
    u64 ai[BPW], af[BPW], ag[BPW], ao[BPW];
    #pragma unroll
    for (int u = 0; u < BPW; u++) {
        u64 xs = pack2(xin[u], xin[u]);
        ai[u] = fma2(xs, wxi2, bi2);    // (x*wx'+b', 0) folded into acc init
        af[u] = fma2(xs, wxf2, bf2);
        ag[u] = fma2(xs, wxg2, bg2);
        ao[u] = fma2(xs, wxo2, bo2);
    }
    #pragma unroll
    for (int q = 0; q < 8; q++) {
        #pragma unroll
        for (int u = 0; u < BPW; u++) {
            ulonglong2 v = ((const ulonglong2*)hr[u])[q];   // 4 h values
            ai[u] = fma2(v.x, wi[2*q], ai[u]);  ai[u] = fma2(v.y, wi[2*q+1], ai[u]);
            af[u] = fma2(v.x, wf[2*q], af[u]);  af[u] = fma2(v.y, wf[2*q+1], af[u]);
            ag[u] = fma2(v.x, wg[2*q], ag[u]);  ag[u] = fma2(v.y, wg[2*q+1], ag[u]);
            ao[u] = fma2(v.x, wq[2*q], ao[u]);  ao[u] = fma2(v.y, wq[2*q+1], ao[u]);
        }
    }
    #pragma unroll
    for (int u = 0; u < BPW; u++) {
        float ig = sigmoid_pre(hadd2(ai[u]));
        float fg = sigmoid_pre(hadd2(af[u]));
        float gg = tanh_hw(hadd2(ag[u]));
        float og = sigmoid_pre(hadd2(ao[u]));
        c[u] = fmaf(fg, c[u], ig * gg);
        h[u] = og * tanh_hw(c[u]);
        hw[u][lane] = h[u];             // STS.32 into the other parity slot
    }
}

__device__ __forceinline__ float warp_proj(float h, float wo, float bo) {
    float v = h * wo;
    v += __shfl_xor_sync(0xffffffffu, v, 16);
    v += __shfl_xor_sync(0xffffffffu, v, 8);
    v += __shfl_xor_sync(0xffffffffu, v, 4);
    v += __shfl_xor_sync(0xffffffffu, v, 2);
    v += __shfl_xor_sync(0xffffffffu, v, 1);
    return v + bo;
}

__global__ void __launch_bounds__(NTHREADS, 2)
feedback_lstm_kernel(const float* __restrict__ X,
                     const float* __restrict__ Wkw, const float* __restrict__ Ukw,
                     const float* __restrict__ bw,
                     const float* __restrict__ Wkd, const float* __restrict__ Ukd,
                     const float* __restrict__ bdv,
                     const float* __restrict__ Wd,  const float* __restrict__ bd,
                     float* __restrict__ out)
{
    __shared__ float sU0[32 * 128];
    __shared__ float sU1[32 * 128];
    __shared__ float sWx0[128], sWx1[128], sB0[128], sB1[128];
    __shared__ float sWo[UNITS];
    __shared__ float sbo;
    __shared__ __align__(16) float hbuf[2][WARPS][BPW][32];
    __shared__ float sX[BPB][T_WARM];

    const int tid = threadIdx.x;
    #pragma unroll 4
    for (int i = tid; i < 32 * 128; i += NTHREADS) {
        sU0[i] = Ukw[i];
        sU1[i] = Ukd[i];
    }
    if (tid < 128) {
        sWx0[tid] = Wkw[tid];
        sB0[tid]  = bw[tid];
        sWx1[tid] = Wkd[tid];
        sB1[tid]  = bdv[tid];
    }
    if (tid < UNITS) sWo[tid] = Wd[tid];
    if (tid == 0) sbo = bd[0];

    // Stage this block's 16 input rows (coalesced).
    const size_t base = (size_t)blockIdx.x * BPB;
    for (int i = tid; i < BPB * T_WARM; i += NTHREADS) {
        int bb = i / T_WARM, t = i % T_WARM;
        sX[bb][t] = X[base * T_WARM + (size_t)bb * T_WARM + t];
    }
    __syncthreads();

    const int lane = tid & 31;
    const int warp = tid >> 5;
    const float wo = sWo[lane];
    const float bo = sbo;

    float h[BPW], c[BPW];
    #pragma unroll
    for (int u = 0; u < BPW; u++) {
        h[u] = 0.f; c[u] = 0.f;
        hbuf[0][warp][u][lane] = 0.f;
    }
    int par = 0;
    const float* hr[BPW];
    float* hw[BPW];

    // ---- Phase 1: warmup, warm weights in registers ----
    // wi[m] = (U[2m][j], U[2m+1][j]) for this lane's unit j, per gate.
    // i/f/o gate weights (incl. wx, b) pre-scaled by 0.5 for sigmoid_pre.
    u64 wi[16], wf[16], wg[16], wq[16];
    u64 wxi2, wxf2, wxg2, wxo2, bi2, bf2, bg2, bo2;
    #pragma unroll
    for (int m = 0; m < 16; m++) {
        wi[m] = pack2(0.5f * sU0[(2*m) * 128 + lane],      0.5f * sU0[(2*m+1) * 128 + lane]);
        wf[m] = pack2(0.5f * sU0[(2*m) * 128 + 32 + lane], 0.5f * sU0[(2*m+1) * 128 + 32 + lane]);
        wg[m] = pack2(       sU0[(2*m) * 128 + 64 + lane],        sU0[(2*m+1) * 128 + 64 + lane]);
        wq[m] = pack2(0.5f * sU0[(2*m) * 128 + 96 + lane], 0.5f * sU0[(2*m+1) * 128 + 96 + lane]);
    }
    wxi2 = pack2(0.5f * sWx0[lane],      0.f);  bi2 = pack2(0.5f * sB0[lane],      0.f);
    wxf2 = pack2(0.5f * sWx0[32 + lane], 0.f);  bf2 = pack2(0.5f * sB0[32 + lane], 0.f);
    wxg2 = pack2(       sWx0[64 + lane], 0.f);  bg2 = pack2(       sB0[64 + lane], 0.f);
    wxo2 = pack2(0.5f * sWx0[96 + lane], 0.f);  bo2 = pack2(0.5f * sB0[96 + lane], 0.f);

    for (int t = 0; t < T_WARM; t++) {
        float xin[BPW];
        #pragma unroll
        for (int u = 0; u < BPW; u++) {
            xin[u] = sX[warp * BPW + u][t];
            hr[u] = hbuf[par][warp][u];
            hw[u] = hbuf[par ^ 1][warp][u];
        }
        stepN(xin, wi, wf, wg, wq, wxi2, wxf2, wxg2, wxo2,
              bi2, bf2, bg2, bo2, hr, hw, h, c, lane);
        par ^= 1;
    }

    float p[BPW], myp[BPW];
    #pragma unroll
    for (int u = 0; u < BPW; u++) {
        p[u] = warp_proj(h[u], wo, bo);
        myp[u] = p[u];
    }

    // ---- Phase 2: decode, reload registers with decode weights ----
    #pragma unroll
    for (int m = 0; m < 16; m++) {
        wi[m] = pack2(0.5f * sU1[(2*m) * 128 + lane],      0.5f * sU1[(2*m+1) * 128 + lane]);
        wf[m] = pack2(0.5f * sU1[(2*m) * 128 + 32 + lane], 0.5f * sU1[(2*m+1) * 128 + 32 + lane]);
        wg[m] = pack2(       sU1[(2*m) * 128 + 64 + lane],        sU1[(2*m+1) * 128 + 64 + lane]);
        wq[m] = pack2(0.5f * sU1[(2*m) * 128 + 96 + lane], 0.5f * sU1[(2*m+1) * 128 + 96 + lane]);
    }
    wxi2 = pack2(0.5f * sWx1[lane],      0.f);  bi2 = pack2(0.5f * sB1[lane],      0.f);
    wxf2 = pack2(0.5f * sWx1[32 + lane], 0.f);  bf2 = pack2(0.5f * sB1[32 + lane], 0.f);
    wxg2 = pack2(       sWx1[64 + lane], 0.f);  bg2 = pack2(       sB1[64 + lane], 0.f);
    wxo2 = pack2(0.5f * sWx1[96 + lane], 0.f);  bo2 = pack2(0.5f * sB1[96 + lane], 0.f);

    for (int s = 1; s < OUT_STEPS; s++) {
        float xin[BPW];
        #pragma unroll
        for (int u = 0; u < BPW; u++) {
            xin[u] = p[u];
            hr[u] = hbuf[par][warp][u];
            hw[u] = hbuf[par ^ 1][warp][u];
        }
        stepN(xin, wi, wf, wg, wq, wxi2, wxf2, wxg2, wxo2,
              bi2, bf2, bg2, bo2, hr, hw, h, c, lane);
        par ^= 1;
        #pragma unroll
        for (int u = 0; u < BPW; u++) {
            p[u] = warp_proj(h[u], wo, bo);
            if (lane == s) myp[u] = p[u];
        }
    }

    if (lane < OUT_STEPS) {
        #pragma unroll
        for (int u = 0; u < BPW; u++)
            out[(base + warp * BPW + u) * OUT_STEPS + lane] = myp[u];
    }
}

extern "C" void kernel_launch(void* const* d_in, const int* in_sizes, int n_in,
                              void* d_out, int out_size) {
    const float* X   = (const float*)d_in[0];
    const float* Wkw = (const float*)d_in[1];
    const float* Ukw = (const float*)d_in[2];
    const float* bw  = (const float*)d_in[3];
    const float* Wkd = (const float*)d_in[4];
    const float* Ukd = (const float*)d_in[5];
    const float* bdv = (const float*)d_in[6];
    const float* Wd  = (const float*)d_in[7];
    const float* bd  = (const float*)d_in[8];
    float* out = (float*)d_out;

    int Bn = in_sizes[0] / T_WARM;            // F == 1
    int grid = (Bn + BPB - 1) / BPB;
    feedback_lstm_kernel<<<grid, NTHREADS>>>(X, Wkw, Ukw, bw, Wkd, Ukd, bdv, Wd, bd, out);
}

// round 14
// speedup vs baseline: 1.5575x; 1.0012x over previous
#include <cuda_runtime.h>

#define T_WARM 48
#define OUT_STEPS 24
#define UNITS 32
#define NTHREADS 128          // 4 warps
#define WARPS (NTHREADS / 32)
#define BPW 4                 // batch elements per warp (ILP)
#define BPB (WARPS * BPW)     // 16 batches per block

typedef unsigned long long u64;

__device__ __forceinline__ u64 pack2(float lo, float hi) {
    u64 r; asm("mov.b64 %0, {%1, %2};" : "=l"(r) : "f"(lo), "f"(hi)); return r;
}
__device__ __forceinline__ u64 fma2(u64 a, u64 b, u64 c) {
    u64 d; asm("fma.rn.f32x2 %0, %1, %2, %3;" : "=l"(d) : "l"(a), "l"(b), "l"(c)); return d;
}
__device__ __forceinline__ float hadd2(u64 v) {
    float lo, hi; asm("mov.b64 {%0, %1}, %2;" : "=f"(lo), "=f"(hi) : "l"(v));
    return lo + hi;
}
// Hardware tanh (MUFU.TANH).
__device__ __forceinline__ float tanh_hw(float x) {
    float r; asm("tanh.approx.f32 %0, %1;" : "=f"(r) : "f"(x)); return r;
}
// Sigmoid with the 0.5 input scaling pre-folded into the weights:
// z' = 0.5*z  ->  sigmoid(z) = 0.5*tanh(z') + 0.5.
__device__ __forceinline__ float sigmoid_pre(float zp) {
    return fmaf(0.5f, tanh_hw(zp), 0.5f);
}

// One step for all BPW batch elements of this warp. Weights in registers,
// shared across batches. h via per-warp smem, one LDS.128 = 4 h values.
// Gate-pair accumulators: acc.lo = even-k sum (+ x/bias folded in),
// acc.hi = odd-k sum; one horizontal add per gate at the end.
__device__ __forceinline__ void stepN(const float (&xin)[BPW],
                                      const u64 (&wi)[16], const u64 (&wf)[16],
                                      const u64 (&wg)[16], const u64 (&wq)[16],
                                      u64 wxi2, u64 wxf2, u64 wxg2, u64 wxo2,
                                      u64 bi2,  u64 bf2,  u64 bg2,  u64 bo2,
                                      const float* (&hr)[BPW], float* (&hw)[BPW],
                                      float (&h)[BPW], float (&c)[BPW], int lane)
{
    __syncwarp();                       // previous step's STS visible
    u64 ai[BPW], af[BPW], ag[BPW], ao[BPW];
    #pragma unroll
    for (int u = 0; u < BPW; u++) {
        u64 xs = pack2(xin[u], xin[u]);
        ai[u] = fma2(xs, wxi2, bi2);    // (x*wx'+b', 0) folded into acc init
        af[u] = fma2(xs, wxf2, bf2);
        ag[u] = fma2(xs, wxg2, bg2);
        ao[u] = fma2(xs, wxo2, bo2);
    }
    #pragma unroll
    for (int q = 0; q < 8; q++) {
        #pragma unroll
        for (int u = 0; u < BPW; u++) {
            ulonglong2 v = ((const ulonglong2*)hr[u])[q];   // 4 h values
            ai[u] = fma2(v.x, wi[2*q], ai[u]);  ai[u] = fma2(v.y, wi[2*q+1], ai[u]);
            af[u] = fma2(v.x, wf[2*q], af[u]);  af[u] = fma2(v.y, wf[2*q+1], af[u]);
            ag[u] = fma2(v.x, wg[2*q], ag[u]);  ag[u] = fma2(v.y, wg[2*q+1], ag[u]);
            ao[u] = fma2(v.x, wq[2*q], ao[u]);  ao[u] = fma2(v.y, wq[2*q+1], ao[u]);
        }
    }
    #pragma unroll
    for (int u = 0; u < BPW; u++) {
        float ig = sigmoid_pre(hadd2(ai[u]));
        float fg = sigmoid_pre(hadd2(af[u]));
        float gg = tanh_hw(hadd2(ag[u]));
        float og = sigmoid_pre(hadd2(ao[u]));
        c[u] = fmaf(fg, c[u], ig * gg);
        h[u] = og * tanh_hw(c[u]);
        hw[u][lane] = h[u];             // STS.32 into the other parity slot
    }
}

__device__ __forceinline__ float warp_proj(float h, float wo, float bo) {
    float v = h * wo;
    v += __shfl_xor_sync(0xffffffffu, v, 16);
    v += __shfl_xor_sync(0xffffffffu, v, 8);
    v += __shfl_xor_sync(0xffffffffu, v, 4);
    v += __shfl_xor_sync(0xffffffffu, v, 2);
    v += __shfl_xor_sync(0xffffffffu, v, 1);
    return v + bo;
}

__global__ void __launch_bounds__(NTHREADS, 2)
feedback_lstm_kernel(const float* __restrict__ X,
                     const float* __restrict__ Wkw, const float* __restrict__ Ukw,
                     const float* __restrict__ bw,
                     const float* __restrict__ Wkd, const float* __restrict__ Ukd,
                     const float* __restrict__ bdv,
                     const float* __restrict__ Wd,  const float* __restrict__ bd,
                     float* __restrict__ out)
{
    __shared__ float sU0[32 * 128];
    __shared__ float sU1[32 * 128];
    __shared__ float sWx0[128], sWx1[128], sB0[128], sB1[128];
    __shared__ float sWo[UNITS];
    __shared__ float sbo;
    __shared__ __align__(16) float hbuf[2][WARPS][BPW][32];
    __shared__ float sX[BPB][T_WARM];

    const int tid = threadIdx.x;
    #pragma unroll 4
    for (int i = tid; i < 32 * 128; i += NTHREADS) {
        sU0[i] = Ukw[i];
        sU1[i] = Ukd[i];
    }
    if (tid < 128) {
        sWx0[tid] = Wkw[tid];
        sB0[tid]  = bw[tid];
        sWx1[tid] = Wkd[tid];
        sB1[tid]  = bdv[tid];
    }
    if (tid < UNITS) sWo[tid] = Wd[tid];
    if (tid == 0) sbo = bd[0];

    // Stage this block's 16 input rows (coalesced).
    const size_t base = (size_t)blockIdx.x * BPB;
    for (int i = tid; i < BPB * T_WARM; i += NTHREADS) {
        int bb = i / T_WARM, t = i % T_WARM;
        sX[bb][t] = X[base * T_WARM + (size_t)bb * T_WARM + t];
    }
    __syncthreads();

    const int lane = tid & 31;
    const int warp = tid >> 5;
    const float wo = sWo[lane];
    const float bo = sbo;

    float h[BPW], c[BPW];
    #pragma unroll
    for (int u = 0; u < BPW; u++) {
        h[u] = 0.f; c[u] = 0.f;
        hbuf[0][warp][u][lane] = 0.f;
    }
    int par = 0;
    const float* hr[BPW];
    float* hw[BPW];

    // ---- Phase 1: warmup, warm weights in registers ----
    // wi[m] = (U[2m][j], U[2m+1][j]) for this lane's unit j, per gate.
    // i/f/o gate weights (incl. wx, b) pre-scaled by 0.5 for sigmoid_pre.
    u64 wi[16], wf[16], wg[16], wq[16];
    u64 wxi2, wxf2, wxg2, wxo2, bi2, bf2, bg2, bo2;
    #pragma unroll
    for (int m = 0; m < 16; m++) {
        wi[m] = pack2(0.5f * sU0[(2*m) * 128 + lane],      0.5f * sU0[(2*m+1) * 128 + lane]);
        wf[m] = pack2(0.5f * sU0[(2*m) * 128 + 32 + lane], 0.5f * sU0[(2*m+1) * 128 + 32 + lane]);
        wg[m] = pack2(       sU0[(2*m) * 128 + 64 + lane],        sU0[(2*m+1) * 128 + 64 + lane]);
        wq[m] = pack2(0.5f * sU0[(2*m) * 128 + 96 + lane], 0.5f * sU0[(2*m+1) * 128 + 96 + lane]);
    }
    wxi2 = pack2(0.5f * sWx0[lane],      0.f);  bi2 = pack2(0.5f * sB0[lane],      0.f);
    wxf2 = pack2(0.5f * sWx0[32 + lane], 0.f);  bf2 = pack2(0.5f * sB0[32 + lane], 0.f);
    wxg2 = pack2(       sWx0[64 + lane], 0.f);  bg2 = pack2(       sB0[64 + lane], 0.f);
    wxo2 = pack2(0.5f * sWx0[96 + lane], 0.f);  bo2 = pack2(0.5f * sB0[96 + lane], 0.f);

    for (int t = 0; t < T_WARM; t++) {
        float xin[BPW];
        #pragma unroll
        for (int u = 0; u < BPW; u++) {
            xin[u] = sX[warp * BPW + u][t];
            hr[u] = hbuf[par][warp][u];
            hw[u] = hbuf[par ^ 1][warp][u];
        }
        stepN(xin, wi, wf, wg, wq, wxi2, wxf2, wxg2, wxo2,
              bi2, bf2, bg2, bo2, hr, hw, h, c, lane);
        par ^= 1;
    }

    float p[BPW], myp[BPW];
    #pragma unroll
    for (int u = 0; u < BPW; u++) {
        p[u] = warp_proj(h[u], wo, bo);
        myp[u] = p[u];
    }

    // ---- Phase 2: decode, reload registers with decode weights ----
    #pragma unroll
    for (int m = 0; m < 16; m++) {
        wi[m] = pack2(0.5f * sU1[(2*m) * 128 + lane],      0.5f * sU1[(2*m+1) * 128 + lane]);
        wf[m] = pack2(0.5f * sU1[(2*m) * 128 + 32 + lane], 0.5f * sU1[(2*m+1) * 128 + 32 + lane]);
        wg[m] = pack2(       sU1[(2*m) * 128 + 64 + lane],        sU1[(2*m+1) * 128 + 64 + lane]);
        wq[m] = pack2(0.5f * sU1[(2*m) * 128 + 96 + lane], 0.5f * sU1[(2*m+1) * 128 + 96 + lane]);
    }
    wxi2 = pack2(0.5f * sWx1[lane],      0.f);  bi2 = pack2(0.5f * sB1[lane],      0.f);
    wxf2 = pack2(0.5f * sWx1[32 + lane], 0.f);  bf2 = pack2(0.5f * sB1[32 + lane], 0.f);
    wxg2 = pack2(       sWx1[64 + lane], 0.f);  bg2 = pack2(       sB1[64 + lane], 0.f);
    wxo2 = pack2(0.5f * sWx1[96 + lane], 0.f);  bo2 = pack2(0.5f * sB1[96 + lane], 0.f);

    for (int s = 1; s < OUT_STEPS; s++) {
        float xin[BPW];
        #pragma unroll
        for (int u = 0; u < BPW; u++) {
            xin[u] = p[u];
            hr[u] = hbuf[par][warp][u];
            hw[u] = hbuf[par ^ 1][warp][u];
        }
        stepN(xin, wi, wf, wg, wq, wxi2, wxf2, wxg2, wxo2,
              bi2, bf2, bg2, bo2, hr, hw, h, c, lane);
        par ^= 1;
        #pragma unroll
        for (int u = 0; u < BPW; u++) {
            p[u] = warp_proj(h[u], wo, bo);
            if (lane == s) myp[u] = p[u];
        }
    }

    if (lane < OUT_STEPS) {
        #pragma unroll
        for (int u = 0; u < BPW; u++)
            out[(base + warp * BPW + u) * OUT_STEPS + lane] = myp[u];
    }
}

extern "C" void kernel_launch(void* const* d_in, const int* in_sizes, int n_in,
                              void* d_out, int out_size) {
    const float* X   = (const float*)d_in[0];
    const float* Wkw = (const float*)d_in[1];
    const float* Ukw = (const float*)d_in[2];
    const float* bw  = (const float*)d_in[3];
    const float* Wkd = (const float*)d_in[4];
    const float* Ukd = (const float*)d_in[5];
    const float* bdv = (const float*)d_in[6];
    const float* Wd  = (const float*)d_in[7];
    const float* bd  = (const float*)d_in[8];
    float* out = (float*)d_out;

    int Bn = in_sizes[0] / T_WARM;            // F == 1
    int grid = (Bn + BPB - 1) / BPB;
    feedback_lstm_kernel<<<grid, NTHREADS>>>(X, Wkw, Ukw, bw, Wkd, Ukd, bdv, Wd, bd, out);
}